// round 2
// baseline (speedup 1.0000x reference)
#include <cuda_runtime.h>
#include <math.h>

// Spiking CNN forward:
//  conv1(1->10,3x3,SAME)->spike(>=1)->pool2 -> conv2(10->20)->spike->pool2 -> z[980]
//  h = z @ Wf1^T ; 32-step LIF(v1)->o1 ; y=o1@Wf2^T ; LIF(v2)->cnt ; softmax(cnt/32)

#define NB 4096
__device__ float g_Z[NB * 980];   // binary conv-stack output (as float)
__device__ float g_H[NB * 100];   // fc1 output

// ===========================================================================
// K1: fused conv stack, one sample per block (160 threads)
// ===========================================================================
__global__ void __launch_bounds__(160)
k1_conv(const float* __restrict__ x, const float* __restrict__ Wc1,
        const float* __restrict__ Wc2)
{
    __shared__ float xs[900];        // padded [30][30] input
    __shared__ float w1s[90];        // conv1 weights [10][9]
    __shared__ float w2s[1800];      // conv2 weights [20][10][9]
    __shared__ float p1s[10 * 272];  // pooled conv1 spikes, [ic][16][17] padded

    const int tid = threadIdx.x;
    const int s   = blockIdx.x;
    const float* xin = x + s * 784;

    for (int i = tid; i < 900; i += 160) {
        int r = i / 30, c = i - r * 30;
        xs[i] = (r >= 1 && r <= 28 && c >= 1 && c <= 28) ? xin[(r - 1) * 28 + (c - 1)] : 0.f;
    }
    if (tid < 90) w1s[tid] = Wc1[tid];
    for (int i = tid; i < 1800; i += 160) w2s[i] = Wc2[i];
    for (int i = tid; i < 2720; i += 160) p1s[i] = 0.f;
    __syncthreads();

    // conv1 + spike + pool : tasks (oc, pooled y, pooled x) = 10*14*14 = 1960
    for (int task = tid; task < 1960; task += 160) {
        int oc = task / 196;
        int pp = task - oc * 196;
        int py = pp / 14, px = pp - py * 14;
        const float* base = xs + (2 * py) * 30 + 2 * px;
        float b[4][4];
        #pragma unroll
        for (int r = 0; r < 4; r++)
            #pragma unroll
            for (int c = 0; c < 4; c++) b[r][c] = base[r * 30 + c];
        float w[9];
        #pragma unroll
        for (int k = 0; k < 9; k++) w[k] = w1s[oc * 9 + k];
        float f = 0.f;
        #pragma unroll
        for (int dy = 0; dy < 2; dy++)
            #pragma unroll
            for (int dx = 0; dx < 2; dx++) {
                float a = 0.f;
                #pragma unroll
                for (int ky = 0; ky < 3; ky++)
                    #pragma unroll
                    for (int kx = 0; kx < 3; kx++)
                        a = fmaf(w[ky * 3 + kx], b[dy + ky][dx + kx], a);
                if (a >= 1.f) f = 1.f;
            }
        p1s[oc * 272 + (py + 1) * 17 + (px + 1)] = f;
    }
    __syncthreads();

    // conv2 + spike + pool : one thread per (oc, pooled row) = 20*7 = 140
    if (tid < 140) {
        int oc = tid / 7, py = tid - oc * 7;
        float acc[2][14];
        #pragma unroll
        for (int i = 0; i < 2; i++)
            #pragma unroll
            for (int j = 0; j < 14; j++) acc[i][j] = 0.f;

        for (int ic = 0; ic < 10; ic++) {
            float a[4][16];
            #pragma unroll
            for (int rr = 0; rr < 4; rr++)
                #pragma unroll
                for (int c = 0; c < 16; c++)
                    a[rr][c] = p1s[ic * 272 + (2 * py + rr) * 17 + c];
            float w[9];
            #pragma unroll
            for (int k = 0; k < 9; k++) w[k] = w2s[oc * 90 + ic * 9 + k];
            #pragma unroll
            for (int orow = 0; orow < 2; orow++)
                #pragma unroll
                for (int ox = 0; ox < 14; ox++) {
                    float t0 = acc[orow][ox];
                    #pragma unroll
                    for (int ky = 0; ky < 3; ky++)
                        #pragma unroll
                        for (int kx = 0; kx < 3; kx++)
                            t0 = fmaf(w[ky * 3 + kx], a[orow + ky][ox + kx], t0);
                    acc[orow][ox] = t0;
                }
        }
        float* zrow = g_Z + s * 980 + oc * 49 + py * 7;
        #pragma unroll
        for (int px = 0; px < 7; px++) {
            bool f = acc[0][2 * px] >= 1.f || acc[0][2 * px + 1] >= 1.f ||
                     acc[1][2 * px] >= 1.f || acc[1][2 * px + 1] >= 1.f;
            zrow[px] = f ? 1.f : 0.f;
        }
    }
}

// ===========================================================================
// K2: H[4096][100] = Z[4096][980] @ Wf1^T   (Wf1 is [100][980])
// BM=32, BN=128 (100 padded), BK=16; 256 threads, each 2m x 8n
// ===========================================================================
__global__ void __launch_bounds__(256)
k2_fc1(const float* __restrict__ Wf1)
{
    __shared__ float Zs[32][17];
    __shared__ float Ws[128][17];
    const int tid = threadIdx.x;
    const int m0  = blockIdx.x * 32;
    const int tx  = tid & 15, ty = tid >> 4;   // ty: 0..15

    float acc[2][8];
    #pragma unroll
    for (int i = 0; i < 2; i++)
        #pragma unroll
        for (int j = 0; j < 8; j++) acc[i][j] = 0.f;

    for (int k0 = 0; k0 < 980; k0 += 16) {
        for (int e = tid; e < 32 * 16; e += 256) {
            int m = e >> 4, k = e & 15, kk = k0 + k;
            Zs[m][k] = (kk < 980) ? g_Z[(m0 + m) * 980 + kk] : 0.f;
        }
        for (int e = tid; e < 128 * 16; e += 256) {
            int n = e >> 4, k = e & 15, kk = k0 + k;
            Ws[n][k] = (n < 100 && kk < 980) ? Wf1[n * 980 + kk] : 0.f;
        }
        __syncthreads();
        #pragma unroll
        for (int k = 0; k < 16; k++) {
            float a0 = Zs[ty][k], a1 = Zs[ty + 16][k];
            float b[8];
            #pragma unroll
            for (int j = 0; j < 8; j++) b[j] = Ws[tx + 16 * j][k];
            #pragma unroll
            for (int j = 0; j < 8; j++) {
                acc[0][j] = fmaf(a0, b[j], acc[0][j]);
                acc[1][j] = fmaf(a1, b[j], acc[1][j]);
            }
        }
        __syncthreads();
    }
    #pragma unroll
    for (int j = 0; j < 8; j++) {
        int n = tx + 16 * j;
        if (n < 100) {
            g_H[(m0 + ty) * 100 + n]      = acc[0][j];
            g_H[(m0 + ty + 16) * 100 + n] = acc[1][j];
        }
    }
}

// ===========================================================================
// K3: per-sample LIF simulation + fc2 + softmax. Block = 320 threads.
// ===========================================================================
__global__ void __launch_bounds__(320)
k3_lif(const float* __restrict__ Wf2, float* __restrict__ out)
{
    __shared__ unsigned mask[100];
    __shared__ float W2s[1000];
    __shared__ float ysm[32][10];
    __shared__ float cs[10];
    const int tid = threadIdx.x;
    const int s   = blockIdx.x;

    for (int e = tid; e < 1000; e += 320) W2s[e] = Wf2[e];

    if (tid < 100) {
        float h = g_H[s * 100 + tid];
        float v = 0.f;
        unsigned m = 0;
        #pragma unroll
        for (int t = 0; t < 32; t++) {
            v += (h - v) * 0.5f;
            if (v >= 1.f) { m |= 1u << t; v = 0.f; }
        }
        mask[tid] = m;
    }
    __syncthreads();

    {   // y[t][i] = sum_j bit(mask_j, t) * Wf2[i][j]
        int t = tid / 10, i = tid - t * 10;
        float a = 0.f;
        #pragma unroll 4
        for (int j = 0; j < 100; j++) {
            float b = (float)((mask[j] >> t) & 1u);
            a = fmaf(b, W2s[i * 100 + j], a);
        }
        ysm[t][i] = a;
    }
    __syncthreads();

    if (tid < 10) {
        float v = 0.f, cnt = 0.f;
        #pragma unroll
        for (int t = 0; t < 32; t++) {
            v += (ysm[t][tid] - v) * 0.5f;
            if (v >= 1.f) { cnt += 1.f; v = 0.f; }
        }
        cs[tid] = cnt * (1.f / 32.f);
    }
    __syncthreads();

    if (tid < 10) {
        float m = cs[0];
        #pragma unroll
        for (int i = 1; i < 10; i++) m = fmaxf(m, cs[i]);
        float sum = 0.f;
        #pragma unroll
        for (int i = 0; i < 10; i++) sum += expf(cs[i] - m);
        out[s * 10 + tid] = expf(cs[tid] - m) / sum;
    }
}

// ===========================================================================
extern "C" void kernel_launch(void* const* d_in, const int* in_sizes, int n_in,
                              void* d_out, int out_size)
{
    const float* x   = (const float*)d_in[0];
    const float* Wc1 = (const float*)d_in[1];
    const float* Wc2 = (const float*)d_in[2];
    const float* Wf1 = (const float*)d_in[3];
    const float* Wf2 = (const float*)d_in[4];
    float* out = (float*)d_out;

    k1_conv<<<NB, 160>>>(x, Wc1, Wc2);
    k2_fc1<<<NB / 32, 256>>>(Wf1);
    k3_lif<<<NB, 320>>>(Wf2, out);
}

// round 3
// speedup vs baseline: 1.0704x; 1.0704x over previous
#include <cuda_runtime.h>
#include <math.h>

// Spiking CNN forward, B=4096:
//  conv1(1->10,3x3,SAME)->spike(>=1)->pool2 -> conv2(10->20)->spike->pool2 -> z[980]
//  h = z @ Wf1^T ; 32-step LIF(v1)->o1 ; y=o1@Wf2^T ; LIF(v2)->cnt ; softmax(cnt/32)

#define NB 4096
typedef unsigned long long u64;
typedef unsigned int uint32;

__device__ float g_Z[NB * 980];   // binary conv-stack output

// ---- packed f32x2 helpers ----
__device__ __forceinline__ u64 splat2(float a){
    u64 r; asm("mov.b64 %0, {%1, %1};" : "=l"(r) : "f"(a)); return r;
}
__device__ __forceinline__ u64 pack2(float a, float b){
    u64 r; asm("mov.b64 %0, {%1, %2};" : "=l"(r) : "f"(a), "f"(b)); return r;
}
__device__ __forceinline__ void unpack2(u64 v, float &x, float &y){
    asm("mov.b64 {%0, %1}, %2;" : "=f"(x), "=f"(y) : "l"(v));
}
__device__ __forceinline__ u64 fma2(u64 a, u64 b, u64 c){
    u64 d; asm("fma.rn.f32x2 %0, %1, %2, %3;" : "=l"(d) : "l"(a), "l"(b), "l"(c));
    return d;
}

// ===========================================================================
// K1: fused conv stack, 2 samples per block, 160 threads, f32x2 over oc-pairs
// Dynamic smem layout (bytes):
//   xs   @ 0      : 2*900 floats            (7200)
//   w1p  @ 7200   : 45 u64                  (360)
//   w2p  @ 7560   : 900 u64                 (7200)
//   p1s  @ 14760  : 2*10*16*34 floats       (43520)  pooled spikes, DUPLICATED pairs
// total 58280
// ===========================================================================
#define K1_SMEM 58280

__global__ void __launch_bounds__(160)
k1_conv(const float* __restrict__ x, const float* __restrict__ Wc1,
        const float* __restrict__ Wc2)
{
    extern __shared__ char smraw[];
    float* xs  = (float*)(smraw);            // [2][30][30]
    u64*   w1p = (u64*)  (smraw + 7200);     // [5 ocp][9]
    u64*   w2p = (u64*)  (smraw + 7560);     // [10 ocp][90]
    float* p1s = (float*)(smraw + 14760);    // [2][10][16][34] (each val twice)

    const int tid = threadIdx.x;
    const int s0  = blockIdx.x * 2;

    // ---- stage inputs / weights ----
    for (int i = tid; i < 1800; i += 160) {
        int sp = i / 900, e = i - sp * 900;
        int r = e / 30, c = e - r * 30;
        float v = 0.f;
        if (r >= 1 && r <= 28 && c >= 1 && c <= 28)
            v = x[(s0 + sp) * 784 + (r - 1) * 28 + (c - 1)];
        xs[i] = v;
    }
    if (tid < 45) {
        int cp = tid / 9, k = tid - cp * 9;
        w1p[tid] = pack2(Wc1[(2 * cp) * 9 + k], Wc1[(2 * cp + 1) * 9 + k]);
    }
    for (int i = tid; i < 900; i += 160) {
        int ocp = i / 90, t = i - ocp * 90;
        w2p[i] = pack2(Wc2[(2 * ocp) * 90 + t], Wc2[(2 * ocp + 1) * 90 + t]);
    }
    for (int i = tid; i < 10880; i += 160) p1s[i] = 0.f;
    __syncthreads();

    // ---- conv1 + spike + pool : tasks (sp, ocp=5, pos=196) = 1960 ----
    for (int task = tid; task < 1960; task += 160) {
        int sp  = task / 980;
        int r   = task - sp * 980;
        int cp  = r / 196;
        int pos = r - cp * 196;
        int py = pos / 14, px = pos - py * 14;
        const float* xb = xs + sp * 900 + (2 * py) * 30 + 2 * px;
        u64 acc[2][2];
        acc[0][0] = acc[0][1] = acc[1][0] = acc[1][1] = 0ull;
        #pragma unroll
        for (int rr = 0; rr < 4; rr++) {
            u64 cc[4];
            #pragma unroll
            for (int c = 0; c < 4; c++) cc[c] = splat2(xb[rr * 30 + c]);
            #pragma unroll
            for (int dy = 0; dy < 2; dy++) {
                int ky = rr - dy;
                if (ky >= 0 && ky <= 2) {
                    #pragma unroll
                    for (int kx = 0; kx < 3; kx++) {
                        u64 w = w1p[cp * 9 + ky * 3 + kx];
                        acc[dy][0] = fma2(cc[kx],     w, acc[dy][0]);
                        acc[dy][1] = fma2(cc[kx + 1], w, acc[dy][1]);
                    }
                }
            }
        }
        float f0 = 0.f, f1 = 0.f, lo, hi;
        #pragma unroll
        for (int dy = 0; dy < 2; dy++)
            #pragma unroll
            for (int dx = 0; dx < 2; dx++) {
                unpack2(acc[dy][dx], lo, hi);
                if (lo >= 1.f) f0 = 1.f;
                if (hi >= 1.f) f1 = 1.f;
            }
        int base = ((sp * 10 + 2 * cp) * 16 + (py + 1)) * 34 + 2 * (px + 1);
        p1s[base]       = f0; p1s[base + 1]   = f0;   // ic plane 2cp
        p1s[base + 544] = f1; p1s[base + 545] = f1;   // ic plane 2cp+1
    }
    __syncthreads();

    // ---- conv2 + spike + pool : tasks (sp, ocp=10, py=7) = 140 ----
    if (tid < 140) {
        int sp  = tid / 70;
        int r70 = tid - sp * 70;
        int ocp = r70 / 7, py = r70 - ocp * 7;
        u64 acc[2][14];
        #pragma unroll
        for (int i = 0; i < 2; i++)
            #pragma unroll
            for (int j = 0; j < 14; j++) acc[i][j] = 0ull;

        const float* pbase = p1s + sp * 5440 + (2 * py) * 34;
        const u64*   wq    = w2p + ocp * 90;

        for (int ic = 0; ic < 10; ic++) {
            u64 w[9];
            #pragma unroll
            for (int k = 0; k < 9; k++) w[k] = wq[ic * 9 + k];
            const float* prow = pbase + ic * 544;
            #pragma unroll
            for (int rr = 0; rr < 4; rr++) {
                u64 arow[16];
                #pragma unroll
                for (int c = 0; c < 16; c++)
                    arow[c] = *(const u64*)(prow + rr * 34 + 2 * c);
                #pragma unroll
                for (int pr = 0; pr < 2; pr++) {
                    int ky = rr - pr;
                    if (ky >= 0 && ky <= 2) {
                        #pragma unroll
                        for (int kx = 0; kx < 3; kx++) {
                            u64 wv = w[ky * 3 + kx];
                            #pragma unroll
                            for (int ox = 0; ox < 14; ox++)
                                acc[pr][ox] = fma2(arow[ox + kx], wv, acc[pr][ox]);
                        }
                    }
                }
            }
        }
        int s = s0 + sp;
        float* z0 = g_Z + s * 980 + (2 * ocp) * 49 + py * 7;
        #pragma unroll
        for (int px = 0; px < 7; px++) {
            float a, b, c, d, e, f, g, h;
            unpack2(acc[0][2 * px],     a, b);
            unpack2(acc[0][2 * px + 1], c, d);
            unpack2(acc[1][2 * px],     e, f);
            unpack2(acc[1][2 * px + 1], g, h);
            z0[px]      = (a >= 1.f || c >= 1.f || e >= 1.f || g >= 1.f) ? 1.f : 0.f;
            z0[49 + px] = (b >= 1.f || d >= 1.f || f >= 1.f || h >= 1.f) ? 1.f : 0.f;
        }
    }
}

// ===========================================================================
// K2K3 fused: per block (256 thr) 32 samples.
//  Phase A: H = Z @ Wf1^T  (f32x2 over n-pairs), h stays in registers
//  Phase B: LIF-1 spike masks (32-bit) -> smem
//  Phase C: Y[t][i] = mask-bits @ Wf2^T  (dense FMA, W2 broadcast from smem)
//  Phase D: v2 LIF sim + softmax (32 threads)
// Dynamic smem (bytes):
//   region0 @ 0     : max( Zs[32][17] f (2176) + Ws2[64][17] u64 (8704) = 10880,
//                          ysm [32][325] f (41600) )            -> 41600
//   Msk  @ 41600    : [32][101] uint32  (12928)
//   W2s  @ 54528    : 1000 floats       (4000)
// total 58528
// ===========================================================================
#define K2_SMEM 58528

__device__ __forceinline__ uint32 lifmask(float h){
    float v = 0.f; uint32 m = 0u;
    #pragma unroll
    for (int t = 0; t < 32; t++) {
        v += (h - v) * 0.5f;
        if (v >= 1.f) { m |= (1u << t); v = 0.f; }
    }
    return m;
}

__global__ void __launch_bounds__(256)
k2k3(const float* __restrict__ Wf1, const float* __restrict__ Wf2,
     float* __restrict__ out)
{
    extern __shared__ char smraw[];
    float*  Zs  = (float*) (smraw);            // [32][17]
    u64*    Ws2 = (u64*)   (smraw + 2176);     // [64 npair][17]
    float*  ysm = (float*) (smraw);            // [32][325] (aliases Zs/Ws2)
    uint32* Msk = (uint32*)(smraw + 41600);    // [32][101]
    float*  W2s = (float*) (smraw + 54528);    // [10][100]

    const int tid = threadIdx.x;
    const int tx  = tid & 15, ty = tid >> 4;
    const int m0  = blockIdx.x * 32;

    for (int e = tid; e < 1000; e += 256) W2s[e] = Wf2[e];

    u64 acc[2][4];
    #pragma unroll
    for (int i = 0; i < 2; i++)
        #pragma unroll
        for (int j = 0; j < 4; j++) acc[i][j] = 0ull;

    // ---- Phase A: GEMM ----
    for (int k0 = 0; k0 < 980; k0 += 16) {
        __syncthreads();
        for (int e = tid; e < 512; e += 256) {
            int m = e >> 4, k = e & 15, kk = k0 + k;
            Zs[m * 17 + k] = (kk < 980) ? g_Z[(m0 + m) * 980 + kk] : 0.f;
        }
        for (int e = tid; e < 1024; e += 256) {
            int p = e >> 4, k = e & 15, kk = k0 + k;
            float w0 = (2 * p     < 100 && kk < 980) ? Wf1[(2 * p)     * 980 + kk] : 0.f;
            float w1 = (2 * p + 1 < 100 && kk < 980) ? Wf1[(2 * p + 1) * 980 + kk] : 0.f;
            Ws2[p * 17 + k] = pack2(w0, w1);
        }
        __syncthreads();
        #pragma unroll
        for (int k = 0; k < 16; k++) {
            u64 s0 = splat2(Zs[(2 * ty)     * 17 + k]);
            u64 s1 = splat2(Zs[(2 * ty + 1) * 17 + k]);
            #pragma unroll
            for (int j = 0; j < 4; j++) {
                u64 b = Ws2[(tx + 16 * j) * 17 + k];
                acc[0][j] = fma2(s0, b, acc[0][j]);
                acc[1][j] = fma2(s1, b, acc[1][j]);
            }
        }
    }

    // ---- Phase B: LIF-1 spike masks ----
    #pragma unroll
    for (int mi = 0; mi < 2; mi++)
        #pragma unroll
        for (int j = 0; j < 4; j++) {
            int np = tx + 16 * j;
            int n0 = 2 * np, n1 = n0 + 1;
            int m  = 2 * ty + mi;
            float h0, h1; unpack2(acc[mi][j], h0, h1);
            if (n0 < 100) Msk[m * 101 + n0] = lifmask(h0);
            if (n1 < 100) Msk[m * 101 + n1] = lifmask(h1);
        }
    __syncthreads();   // Msk ready; GEMM smem reads done -> ysm may be written

    // ---- Phase C: y[t][i] per (m, t) ----
    {
        int m  = tid >> 3;     // 0..31
        int t8 = tid & 7;      // handles t8, t8+8, t8+16, t8+24
        float y[4][10];
        #pragma unroll
        for (int q = 0; q < 4; q++)
            #pragma unroll
            for (int i = 0; i < 10; i++) y[q][i] = 0.f;
        for (int j = 0; j < 100; j++) {
            uint32 mk = Msk[m * 101 + j];
            float b0 = (float)((mk >> t8) & 1u);
            float b1 = (float)((mk >> (t8 + 8))  & 1u);
            float b2 = (float)((mk >> (t8 + 16)) & 1u);
            float b3 = (float)((mk >> (t8 + 24)) & 1u);
            #pragma unroll
            for (int i = 0; i < 10; i++) {
                float w = W2s[i * 100 + j];
                y[0][i] = fmaf(b0, w, y[0][i]);
                y[1][i] = fmaf(b1, w, y[1][i]);
                y[2][i] = fmaf(b2, w, y[2][i]);
                y[3][i] = fmaf(b3, w, y[3][i]);
            }
        }
        #pragma unroll
        for (int q = 0; q < 4; q++) {
            int t = t8 + 8 * q;
            #pragma unroll
            for (int i = 0; i < 10; i++)
                ysm[m * 325 + t * 10 + i] = y[q][i];
        }
    }
    __syncthreads();

    // ---- Phase D: v2 LIF + softmax (one thread per sample) ----
    if (tid < 32) {
        int mm = tid;
        float v2[10], cnt[10];
        #pragma unroll
        for (int i = 0; i < 10; i++) { v2[i] = 0.f; cnt[i] = 0.f; }
        for (int t = 0; t < 32; t++) {
            #pragma unroll
            for (int i = 0; i < 10; i++) {
                float yv = ysm[mm * 325 + t * 10 + i];
                v2[i] += (yv - v2[i]) * 0.5f;
                if (v2[i] >= 1.f) { cnt[i] += 1.f; v2[i] = 0.f; }
            }
        }
        float c[10], mx = -1e30f;
        #pragma unroll
        for (int i = 0; i < 10; i++) { c[i] = cnt[i] * (1.f / 32.f); mx = fmaxf(mx, c[i]); }
        float sum = 0.f, ex[10];
        #pragma unroll
        for (int i = 0; i < 10; i++) { ex[i] = expf(c[i] - mx); sum += ex[i]; }
        float inv = 1.f / sum;
        #pragma unroll
        for (int i = 0; i < 10; i++) out[(m0 + mm) * 10 + i] = ex[i] * inv;
    }
}

// ===========================================================================
extern "C" void kernel_launch(void* const* d_in, const int* in_sizes, int n_in,
                              void* d_out, int out_size)
{
    const float* x   = (const float*)d_in[0];
    const float* Wc1 = (const float*)d_in[1];
    const float* Wc2 = (const float*)d_in[2];
    const float* Wf1 = (const float*)d_in[3];
    const float* Wf2 = (const float*)d_in[4];
    float* out = (float*)d_out;

    cudaFuncSetAttribute(k1_conv, cudaFuncAttributeMaxDynamicSharedMemorySize, K1_SMEM);
    cudaFuncSetAttribute(k2k3,    cudaFuncAttributeMaxDynamicSharedMemorySize, K2_SMEM);

    k1_conv<<<NB / 2, 160, K1_SMEM>>>(x, Wc1, Wc2);
    k2k3<<<NB / 32, 256, K2_SMEM>>>(Wf1, Wf2, out);
}